// round 12
// baseline (speedup 1.0000x reference)
#include <cuda_runtime.h>
#include <cuda_bf16.h>
#include <cstdint>

#define BATCH 8
#define CDIM  256
#define NTOK  4096

typedef unsigned int u32;

// Scratch (allocation-free rule)
__device__ float          g_q[BATCH * NTOK * 32];    // [b][n][32] tf32-rounded
__device__ float          g_k[BATCH * NTOK * 32];    // [b][n][32] tf32-rounded
__device__ __nv_bfloat16  g_v[(size_t)BATCH * NTOK * CDIM];  // [b][n][256] bf16

__device__ __forceinline__ u32 smem_u32(const void* p) {
    u32 a;
    asm("{ .reg .u64 t; cvta.to.shared.u64 t, %1; cvt.u32.u64 %0, t; }" : "=r"(a) : "l"(p));
    return a;
}
__device__ __forceinline__ float f2tf32f(float x) {
    u32 u; asm("cvt.rna.tf32.f32 %0, %1;" : "=r"(u) : "f"(x));
    return __uint_as_float(u);
}
__device__ __forceinline__ u32 f2tf32u(float x) {
    u32 u; asm("cvt.rna.tf32.f32 %0, %1;" : "=r"(u) : "f"(x));
    return u;
}

#define CP16(dst, src) \
    asm volatile("cp.async.cg.shared.global [%0], [%1], 16;" :: "r"(dst), "l"(src))
#define CP_COMMIT() asm volatile("cp.async.commit_group;" ::: "memory")
#define CP_WAIT(n)  asm volatile("cp.async.wait_group %0;" :: "n"(n) : "memory")

// ---------------------------------------------------------------------------
// Kernel 1: tensor-core QKV projection (tf32 m16n8k8). Unchanged from r4.
// ---------------------------------------------------------------------------
#define QW_STR 36
#define QX_STR 260
#define Q_BUF  (64 * QW_STR * 4 + 32 * QX_STR * 4)   // 42496
#define Q_SMEM (2 * Q_BUF)                            // 84992

__global__ __launch_bounds__(256, 2) void qkv_kernel(
    const float* __restrict__ x,
    const float* __restrict__ Wq, const float* __restrict__ bq,
    const float* __restrict__ Wk, const float* __restrict__ bk,
    const float* __restrict__ Wv, const float* __restrict__ bv)
{
    extern __shared__ __align__(16) char qsm[];
    const int b      = blockIdx.z;
    const int o_base = blockIdx.y * 64;
    const int n_base = blockIdx.x * 256;
    const int tid    = threadIdx.x;
    const int w      = tid >> 5, lane = tid & 31;
    const int grp    = lane >> 2, tig = lane & 3;
    const int wo     = w & 3, wn = w >> 2;
    const float* xb  = x + (size_t)b * CDIM * NTOK;
    const u32 sbase  = smem_u32(qsm);

    const float* wrowp[2];
    int wcol[2];
    int wdst[2];
#pragma unroll
    for (int u = 0; u < 2; ++u) {
        const int idx = tid + u * 256;
        const int row = idx >> 3;
        const int og  = o_base + row;
        wrowp[u] = (og < 32) ? (Wq + (size_t)og * CDIM)
                 : ((og < 64) ? (Wk + (size_t)(og - 32) * CDIM)
                              : (Wv + (size_t)(og - 64) * CDIM));
        wcol[u]  = (idx & 7) * 4;
        wdst[u]  = row * (QW_STR * 4) + (idx & 7) * 16;
    }

    float acc[16][4];
#pragma unroll
    for (int nt = 0; nt < 16; ++nt)
#pragma unroll
        for (int q = 0; q < 4; ++q) acc[nt][q] = 0.0f;

#define QKV_ISSUE(s, sel) do {                                                   \
        const u32 wb = sbase + (sel) * Q_BUF;                                    \
        _Pragma("unroll")                                                        \
        for (int u = 0; u < 2; ++u)                                              \
            CP16(wb + wdst[u], wrowp[u] + (s) * 32 + wcol[u]);                   \
        const u32 xs = wb + 64 * QW_STR * 4;                                     \
        _Pragma("unroll")                                                        \
        for (int u = 0; u < 8; ++u) {                                            \
            const int idx = tid + u * 256;                                       \
            const int cr = idx >> 6, nc = (idx & 63) * 4;                        \
            CP16(xs + cr * (QX_STR * 4) + nc * 4,                                \
                 xb + (size_t)((s) * 32 + cr) * NTOK + n_base + nc);             \
        }                                                                        \
    } while (0)

    QKV_ISSUE(0, 0); CP_COMMIT();

#pragma unroll 1
    for (int s = 0; s < 8; ++s) {
        if (s < 7) { QKV_ISSUE(s + 1, (s + 1) & 1); CP_COMMIT(); CP_WAIT(1); }
        else       { CP_WAIT(0); }
        __syncthreads();
        const float* sW = (const float*)(qsm + (s & 1) * Q_BUF);
        const float* sX = sW + 64 * QW_STR;
#pragma unroll
        for (int ks = 0; ks < 4; ++ks) {
            const int c = ks * 8 + tig;
            u32 a0 = f2tf32u(sW[(wo * 16 + grp) * QW_STR + c]);
            u32 a1 = f2tf32u(sW[(wo * 16 + grp + 8) * QW_STR + c]);
            u32 a2 = f2tf32u(sW[(wo * 16 + grp) * QW_STR + c + 4]);
            u32 a3 = f2tf32u(sW[(wo * 16 + grp + 8) * QW_STR + c + 4]);
#pragma unroll
            for (int nt = 0; nt < 16; ++nt) {
                const int n = wn * 128 + nt * 8 + grp;
                const u32 b0 = __float_as_uint(sX[(ks * 8 + tig) * QX_STR + n]);
                const u32 b1 = __float_as_uint(sX[(ks * 8 + tig + 4) * QX_STR + n]);
                asm volatile(
                    "mma.sync.aligned.m16n8k8.row.col.f32.tf32.tf32.f32 "
                    "{%0,%1,%2,%3}, {%4,%5,%6,%7}, {%8,%9}, {%0,%1,%2,%3};"
                    : "+f"(acc[nt][0]), "+f"(acc[nt][1]), "+f"(acc[nt][2]), "+f"(acc[nt][3])
                    : "r"(a0), "r"(a1), "r"(a2), "r"(a3), "r"(b0), "r"(b1));
            }
        }
        __syncthreads();
    }

    {
        const int o0 = o_base + wo * 16 + grp;
        const int o1 = o0 + 8;
        const float bias0 = (o0 < 32) ? bq[o0] : ((o0 < 64) ? bk[o0 - 32] : bv[o0 - 64]);
        const float bias1 = (o1 < 32) ? bq[o1] : ((o1 < 64) ? bk[o1 - 32] : bv[o1 - 64]);
#pragma unroll
        for (int nt = 0; nt < 16; ++nt) {
            acc[nt][0] += bias0; acc[nt][1] += bias0;
            acc[nt][2] += bias1; acc[nt][3] += bias1;
        }
    }

    float* stage = (float*)qsm;
    __syncthreads();
#pragma unroll
    for (int nt = 0; nt < 16; ++nt) {
        const int n = wn * 128 + nt * 8 + 2 * tig;
        const int o0 = wo * 16 + grp;
        stage[n * 68 + o0]           = acc[nt][0];
        stage[(n + 1) * 68 + o0]     = acc[nt][1];
        stage[n * 68 + o0 + 8]       = acc[nt][2];
        stage[(n + 1) * 68 + o0 + 8] = acc[nt][3];
    }
    __syncthreads();

    {
        const int n = tid;
        const float* sr = stage + n * 68;
        if (o_base == 0) {
            float* dq = g_q + ((size_t)b * NTOK + n_base + n) * 32;
            float* dk = g_k + ((size_t)b * NTOK + n_base + n) * 32;
#pragma unroll
            for (int c4 = 0; c4 < 8; ++c4) {
                float4 v = *(const float4*)(sr + c4 * 4);
                *(float4*)(dq + c4 * 4) = make_float4(f2tf32f(v.x), f2tf32f(v.y),
                                                      f2tf32f(v.z), f2tf32f(v.w));
                float4 u = *(const float4*)(sr + 32 + c4 * 4);
                *(float4*)(dk + c4 * 4) = make_float4(f2tf32f(u.x), f2tf32f(u.y),
                                                      f2tf32f(u.z), f2tf32f(u.w));
            }
        } else {
            __nv_bfloat16* dv = g_v + ((size_t)b * NTOK + n_base + n) * CDIM + (o_base - 64);
#pragma unroll
            for (int c4 = 0; c4 < 16; ++c4) {
                float4 v = *(const float4*)(sr + c4 * 4);
                u32 p01, p23;
                asm("cvt.rn.bf16x2.f32 %0, %1, %2;" : "=r"(p01) : "f"(v.y), "f"(v.x));
                asm("cvt.rn.bf16x2.f32 %0, %1, %2;" : "=r"(p23) : "f"(v.w), "f"(v.z));
                *(uint2*)(dv + c4 * 4) = make_uint2(p01, p23);
            }
        }
    }
}

// ---------------------------------------------------------------------------
// Kernel 2: warp-MMA flash attention, 512 thr / 16 warps, lagged pipeline,
// latency-aware inner scheduling:
//   S phase ks-outer (batch 8 LDS, then 4 independent HMMAs),
//   O phase kj-outer with 2-deep B-fragment register double buffer.
// Warp (wr = w&7: 16-row group, wc = w>>3: half).
// One __syncthreads per iter; 4-deep KV cp.async ring; regs ~120 (no spill).
// ---------------------------------------------------------------------------
#define KSTR 36        // K smem row stride (floats)
#define VSTR 264       // V smem row stride (bf16)
#define PSTR 72        // P smem row stride (bf16)
#define A_BUF 43008    // 64*36*4 + 64*264*2
#define PB_SZ (128 * PSTR * 2)           // 18432
#define OFF_P  (4 * A_BUF)               // 172032
#define OFF_SL (OFF_P + 2 * PB_SZ)       // 208896
#define A_SMEM (OFF_SL + 256 * 4)        // 209920

#define LDSM_T(r, addr) \
    asm volatile("ldmatrix.sync.aligned.m8n8.x4.trans.shared.b16 {%0,%1,%2,%3}, [%4];" \
        : "=r"((r)[0]), "=r"((r)[1]), "=r"((r)[2]), "=r"((r)[3]) : "r"(addr))

#define HMMA_BF16(d, a, b0_, b1_) \
    asm volatile("mma.sync.aligned.m16n8k16.row.col.f32.bf16.bf16.f32 " \
        "{%0,%1,%2,%3}, {%4,%5,%6,%7}, {%8,%9}, {%0,%1,%2,%3};" \
        : "+f"((d)[0]), "+f"((d)[1]), "+f"((d)[2]), "+f"((d)[3]) \
        : "r"((a)[0]), "r"((a)[1]), "r"((a)[2]), "r"((a)[3]), "r"(b0_), "r"(b1_))

__global__ __launch_bounds__(512, 1) void attn_kernel(
    const float* __restrict__ x,
    const float* __restrict__ gamma,
    float* __restrict__ out)
{
    extern __shared__ __align__(16) char smem[];
    const int tid  = threadIdx.x;
    const int w    = tid >> 5;
    const int lane = tid & 31;
    const int grp  = lane >> 2;
    const int tig  = lane & 3;
    const int wr   = w & 7;     // row group (16 rows)
    const int wc   = w >> 3;    // half
    const int b    = blockIdx.y;
    const int ibase = blockIdx.x * 128;
    const u32 sbase = smem_u32(smem);

#define ATTN_ISSUE(t, sel) do {                                                  \
        const u32 kb_ = sbase + (u32)(sel) * A_BUF;                              \
        const float4* gk = (const float4*)(g_k + ((size_t)b * NTOK + (t) * 64) * 32); \
        CP16(kb_ + (tid >> 3) * (KSTR * 4) + (tid & 7) * 16, gk + tid);          \
        const u32 vb_ = kb_ + 64 * KSTR * 4;                                     \
        const uint4* gv = (const uint4*)(g_v + ((size_t)b * NTOK + (t) * 64) * CDIM); \
        _Pragma("unroll")                                                        \
        for (int u = 0; u < 4; ++u) {                                            \
            const int idx = tid + u * 512;                                       \
            CP16(vb_ + (idx >> 5) * (VSTR * 2) + (idx & 31) * 16, gv + idx);     \
        }                                                                        \
    } while (0)

    ATTN_ISSUE(0, 0); CP_COMMIT();
    ATTN_ISSUE(1, 1); CP_COMMIT();

    // ---- Q A-fragments (tf32 m16n8k8): rows ibase + wr*16 + {grp, grp+8}
    u32 qa[4][4];
    {
        const float* Qb = g_q + ((size_t)b * NTOK + ibase + wr * 16) * 32;
#pragma unroll
        for (int ks = 0; ks < 4; ++ks) {
            const int c = ks * 8 + tig;
            qa[ks][0] = __float_as_uint(Qb[grp * 32 + c]);
            qa[ks][1] = __float_as_uint(Qb[(grp + 8) * 32 + c]);
            qa[ks][2] = __float_as_uint(Qb[grp * 32 + c + 4]);
            qa[ks][3] = __float_as_uint(Qb[(grp + 8) * 32 + c + 4]);
        }
    }

    float acc[16][4];   // O accum: cols wc*128 .. +127
#pragma unroll
    for (int i = 0; i < 16; ++i)
#pragma unroll
        for (int q = 0; q < 4; ++q) acc[i][q] = 0.0f;
    float l0 = 0.0f, l1 = 0.0f;

    const int prow0 = (wr * 16 + grp) * (PSTR / 2) + wc * 16;
    const u32 paoff = (u32)(((wr * 16 + (lane & 15)) * PSTR + ((lane >> 4) & 1) * 8) * 2);
    const u32 vfoff = (u32)(((lane & 15) * VSTR + ((lane >> 4) * 8) + wc * 128) * 2);

#pragma unroll 1
    for (int t = 0; t <= 64; ++t) {
        if (t < 63)       CP_WAIT(1);
        else if (t == 63) CP_WAIT(0);
        __syncthreads();
        if (t + 2 < 64) { ATTN_ISSUE(t + 2, (t + 2) & 3); CP_COMMIT(); }

        // ---- S(t): ks-outer; 8 LDS batch then 4 independent HMMAs
        if (t < 64) {
            const float* Ks = (const float*)(smem + (t & 3) * A_BUF);
            u32* sP = (u32*)(smem + OFF_P + (t & 1) * PB_SZ);
            float sac[4][4];
#pragma unroll
            for (int n_ = 0; n_ < 4; ++n_) {
                sac[n_][0] = sac[n_][1] = sac[n_][2] = sac[n_][3] = 0.0f;
            }
#pragma unroll
            for (int ks = 0; ks < 4; ++ks) {
                u32 kb[4][2];
#pragma unroll
                for (int ntl = 0; ntl < 4; ++ntl) {
                    const int ntg = wc * 4 + ntl;
                    kb[ntl][0] = __float_as_uint(Ks[(ntg * 8 + grp) * KSTR + ks * 8 + tig]);
                    kb[ntl][1] = __float_as_uint(Ks[(ntg * 8 + grp) * KSTR + ks * 8 + 4 + tig]);
                }
#pragma unroll
                for (int ntl = 0; ntl < 4; ++ntl) {
                    asm volatile(
                        "mma.sync.aligned.m16n8k8.row.col.f32.tf32.tf32.f32 "
                        "{%0,%1,%2,%3}, {%4,%5,%6,%7}, {%8,%9}, {%0,%1,%2,%3};"
                        : "+f"(sac[ntl][0]), "+f"(sac[ntl][1]),
                          "+f"(sac[ntl][2]), "+f"(sac[ntl][3])
                        : "r"(qa[ks][0]), "r"(qa[ks][1]), "r"(qa[ks][2]), "r"(qa[ks][3]),
                          "r"(kb[ntl][0]), "r"(kb[ntl][1]));
                }
            }
#pragma unroll
            for (int ntl = 0; ntl < 4; ++ntl) {
                const float s0 = __expf(sac[ntl][0]);
                const float s1 = __expf(sac[ntl][1]);
                const float s2 = __expf(sac[ntl][2]);
                const float s3 = __expf(sac[ntl][3]);
                l0 += s0 + s1;
                l1 += s2 + s3;
                u32 k0, k1;
                asm("cvt.rn.bf16x2.f32 %0, %1, %2;" : "=r"(k0) : "f"(s1), "f"(s0));
                asm("cvt.rn.bf16x2.f32 %0, %1, %2;" : "=r"(k1) : "f"(s3), "f"(s2));
                const int pi = prow0 + ntl * 4 + tig;
                sP[pi]                  = k0;
                sP[pi + 8 * (PSTR / 2)] = k1;
            }
        }

        // ---- O(t-1): kj-outer, cb-inner, B-frag register double buffer
        if (t > 0) {
            const u32 pabase = sbase + OFF_P + (u32)((t - 1) & 1) * PB_SZ + paoff;
            u32 pa[4][4];
#pragma unroll
            for (int kj = 0; kj < 4; ++kj) {
                asm volatile(
                    "ldmatrix.sync.aligned.m8n8.x4.shared.b16 {%0,%1,%2,%3}, [%4];"
                    : "=r"(pa[kj][0]), "=r"(pa[kj][1]), "=r"(pa[kj][2]), "=r"(pa[kj][3])
                    : "r"(pabase + (u32)(kj * 32)));
            }
            const u32 lmbase = sbase + (u32)((t - 1) & 3) * A_BUF + 64 * KSTR * 4 + vfoff;
#pragma unroll
            for (int kj = 0; kj < 4; ++kj) {
                const u32 kjb = lmbase + (u32)(kj * 16 * (VSTR * 2));
                u32 bf0[4], bf1[4];
                LDSM_T(bf0, kjb);
#pragma unroll
                for (int cb = 0; cb < 8; ++cb) {
                    if (cb & 1) {
                        if (cb < 7) LDSM_T(bf0, kjb + (u32)((cb + 1) * 32));
                        HMMA_BF16(acc[cb * 2],     pa[kj], bf1[0], bf1[1]);
                        HMMA_BF16(acc[cb * 2 + 1], pa[kj], bf1[2], bf1[3]);
                    } else {
                        if (cb < 7) LDSM_T(bf1, kjb + (u32)((cb + 1) * 32));
                        HMMA_BF16(acc[cb * 2],     pa[kj], bf0[0], bf0[1]);
                        HMMA_BF16(acc[cb * 2 + 1], pa[kj], bf0[2], bf0[3]);
                    }
                }
            }
        }
    }
    __syncthreads();

    // ---- combine partial row sums (two j-halves) via smem
    float* sL = (float*)(smem + OFF_SL);
    l0 += __shfl_xor_sync(0xFFFFFFFFu, l0, 1);
    l0 += __shfl_xor_sync(0xFFFFFFFFu, l0, 2);
    l1 += __shfl_xor_sync(0xFFFFFFFFu, l1, 1);
    l1 += __shfl_xor_sync(0xFFFFFFFFu, l1, 2);
    if (tig == 0) {
        sL[wc * 128 + wr * 16 + grp]     = l0;
        sL[wc * 128 + wr * 16 + grp + 8] = l1;
    }
    __syncthreads();
    const float gval = gamma[0];
    const float invl0 = gval / (sL[wr * 16 + grp]     + sL[128 + wr * 16 + grp]);
    const float invl1 = gval / (sL[wr * 16 + grp + 8] + sL[128 + wr * 16 + grp + 8]);
    __syncthreads();

    // ---- epilogue: 4 chunks of 64 cols x 128 i, staged via smem
    float* stage = (float*)smem;
#pragma unroll 1
    for (int cc = 0; cc < 4; ++cc) {
        if (wc == (cc >> 1)) {
            const int half = cc & 1;
#pragma unroll
            for (int nt8 = 0; nt8 < 8; ++nt8) {
                const int a = half * 8 + nt8;
                const int c0 = nt8 * 8 + 2 * tig;
                const int i0 = wr * 16 + grp;
                stage[c0 * 132 + i0]           = acc[a][0] * invl0;
                stage[(c0 + 1) * 132 + i0]     = acc[a][1] * invl0;
                stage[c0 * 132 + i0 + 8]       = acc[a][2] * invl1;
                stage[(c0 + 1) * 132 + i0 + 8] = acc[a][3] * invl1;
            }
        }
        __syncthreads();
        {
            const int cl  = tid >> 3;
            const int cg  = cc * 64 + cl;
            const int ii0 = (tid & 7) * 16;
            const size_t row = ((size_t)b * CDIM + cg) * NTOK + ibase;
#pragma unroll
            for (int u = 0; u < 4; ++u) {
                const int i = ii0 + u * 4;
                const float4 sv = *(const float4*)&stage[cl * 132 + i];
                const float4 xv = *(const float4*)(x + row + i);
                *(float4*)(out + row + i) =
                    make_float4(sv.x + xv.x, sv.y + xv.y, sv.z + xv.z, sv.w + xv.w);
            }
        }
        __syncthreads();
    }
}

// ---------------------------------------------------------------------------
extern "C" void kernel_launch(void* const* d_in, const int* in_sizes, int n_in,
                              void* d_out, int out_size)
{
    const float* x     = (const float*)d_in[0];
    const float* Wq    = (const float*)d_in[1];
    const float* bq    = (const float*)d_in[2];
    const float* Wk    = (const float*)d_in[3];
    const float* bk    = (const float*)d_in[4];
    const float* Wv    = (const float*)d_in[5];
    const float* bv    = (const float*)d_in[6];
    const float* gamma = (const float*)d_in[7];
    float* out = (float*)d_out;

    cudaFuncSetAttribute(qkv_kernel, cudaFuncAttributeMaxDynamicSharedMemorySize, Q_SMEM);
    cudaFuncSetAttribute(attn_kernel, cudaFuncAttributeMaxDynamicSharedMemorySize, A_SMEM);

    qkv_kernel<<<dim3(NTOK / 256, 5, BATCH), 256, Q_SMEM>>>(x, Wq, bq, Wk, bk, Wv, bv);
    attn_kernel<<<dim3(NTOK / 128, BATCH), 512, A_SMEM>>>(x, gamma, out);
}

// round 13
// speedup vs baseline: 1.3264x; 1.3264x over previous
#include <cuda_runtime.h>
#include <cuda_bf16.h>
#include <cstdint>

#define BATCH 8
#define CDIM  256
#define NTOK  4096

typedef unsigned int u32;

// Scratch (allocation-free rule)
__device__ float          g_q[BATCH * NTOK * 32];    // [b][n][32] tf32-rounded
__device__ float          g_k[BATCH * NTOK * 32];    // [b][n][32] tf32-rounded
__device__ __nv_bfloat16  g_v[(size_t)BATCH * NTOK * CDIM];  // [b][n][256] bf16

__device__ __forceinline__ u32 smem_u32(const void* p) {
    u32 a;
    asm("{ .reg .u64 t; cvta.to.shared.u64 t, %1; cvt.u32.u64 %0, t; }" : "=r"(a) : "l"(p));
    return a;
}
__device__ __forceinline__ float f2tf32f(float x) {
    u32 u; asm("cvt.rna.tf32.f32 %0, %1;" : "=r"(u) : "f"(x));
    return __uint_as_float(u);
}
__device__ __forceinline__ u32 f2tf32u(float x) {
    u32 u; asm("cvt.rna.tf32.f32 %0, %1;" : "=r"(u) : "f"(x));
    return u;
}

#define CP16(dst, src) \
    asm volatile("cp.async.cg.shared.global [%0], [%1], 16;" :: "r"(dst), "l"(src))
#define CP_COMMIT() asm volatile("cp.async.commit_group;" ::: "memory")
#define CP_WAIT(n)  asm volatile("cp.async.wait_group %0;" :: "n"(n) : "memory")

// ---------------------------------------------------------------------------
// Kernel 1: tensor-core QKV projection (tf32 m16n8k8). Unchanged from r4.
// ---------------------------------------------------------------------------
#define QW_STR 36
#define QX_STR 260
#define Q_BUF  (64 * QW_STR * 4 + 32 * QX_STR * 4)   // 42496
#define Q_SMEM (2 * Q_BUF)                            // 84992

__global__ __launch_bounds__(256, 2) void qkv_kernel(
    const float* __restrict__ x,
    const float* __restrict__ Wq, const float* __restrict__ bq,
    const float* __restrict__ Wk, const float* __restrict__ bk,
    const float* __restrict__ Wv, const float* __restrict__ bv)
{
    extern __shared__ __align__(16) char qsm[];
    const int b      = blockIdx.z;
    const int o_base = blockIdx.y * 64;
    const int n_base = blockIdx.x * 256;
    const int tid    = threadIdx.x;
    const int w      = tid >> 5, lane = tid & 31;
    const int grp    = lane >> 2, tig = lane & 3;
    const int wo     = w & 3, wn = w >> 2;
    const float* xb  = x + (size_t)b * CDIM * NTOK;
    const u32 sbase  = smem_u32(qsm);

    const float* wrowp[2];
    int wcol[2];
    int wdst[2];
#pragma unroll
    for (int u = 0; u < 2; ++u) {
        const int idx = tid + u * 256;
        const int row = idx >> 3;
        const int og  = o_base + row;
        wrowp[u] = (og < 32) ? (Wq + (size_t)og * CDIM)
                 : ((og < 64) ? (Wk + (size_t)(og - 32) * CDIM)
                              : (Wv + (size_t)(og - 64) * CDIM));
        wcol[u]  = (idx & 7) * 4;
        wdst[u]  = row * (QW_STR * 4) + (idx & 7) * 16;
    }

    float acc[16][4];
#pragma unroll
    for (int nt = 0; nt < 16; ++nt)
#pragma unroll
        for (int q = 0; q < 4; ++q) acc[nt][q] = 0.0f;

#define QKV_ISSUE(s, sel) do {                                                   \
        const u32 wb = sbase + (sel) * Q_BUF;                                    \
        _Pragma("unroll")                                                        \
        for (int u = 0; u < 2; ++u)                                              \
            CP16(wb + wdst[u], wrowp[u] + (s) * 32 + wcol[u]);                   \
        const u32 xs = wb + 64 * QW_STR * 4;                                     \
        _Pragma("unroll")                                                        \
        for (int u = 0; u < 8; ++u) {                                            \
            const int idx = tid + u * 256;                                       \
            const int cr = idx >> 6, nc = (idx & 63) * 4;                        \
            CP16(xs + cr * (QX_STR * 4) + nc * 4,                                \
                 xb + (size_t)((s) * 32 + cr) * NTOK + n_base + nc);             \
        }                                                                        \
    } while (0)

    QKV_ISSUE(0, 0); CP_COMMIT();

#pragma unroll 1
    for (int s = 0; s < 8; ++s) {
        if (s < 7) { QKV_ISSUE(s + 1, (s + 1) & 1); CP_COMMIT(); CP_WAIT(1); }
        else       { CP_WAIT(0); }
        __syncthreads();
        const float* sW = (const float*)(qsm + (s & 1) * Q_BUF);
        const float* sX = sW + 64 * QW_STR;
#pragma unroll
        for (int ks = 0; ks < 4; ++ks) {
            const int c = ks * 8 + tig;
            u32 a0 = f2tf32u(sW[(wo * 16 + grp) * QW_STR + c]);
            u32 a1 = f2tf32u(sW[(wo * 16 + grp + 8) * QW_STR + c]);
            u32 a2 = f2tf32u(sW[(wo * 16 + grp) * QW_STR + c + 4]);
            u32 a3 = f2tf32u(sW[(wo * 16 + grp + 8) * QW_STR + c + 4]);
#pragma unroll
            for (int nt = 0; nt < 16; ++nt) {
                const int n = wn * 128 + nt * 8 + grp;
                const u32 b0 = __float_as_uint(sX[(ks * 8 + tig) * QX_STR + n]);
                const u32 b1 = __float_as_uint(sX[(ks * 8 + tig + 4) * QX_STR + n]);
                asm volatile(
                    "mma.sync.aligned.m16n8k8.row.col.f32.tf32.tf32.f32 "
                    "{%0,%1,%2,%3}, {%4,%5,%6,%7}, {%8,%9}, {%0,%1,%2,%3};"
                    : "+f"(acc[nt][0]), "+f"(acc[nt][1]), "+f"(acc[nt][2]), "+f"(acc[nt][3])
                    : "r"(a0), "r"(a1), "r"(a2), "r"(a3), "r"(b0), "r"(b1));
            }
        }
        __syncthreads();
    }

    {
        const int o0 = o_base + wo * 16 + grp;
        const int o1 = o0 + 8;
        const float bias0 = (o0 < 32) ? bq[o0] : ((o0 < 64) ? bk[o0 - 32] : bv[o0 - 64]);
        const float bias1 = (o1 < 32) ? bq[o1] : ((o1 < 64) ? bk[o1 - 32] : bv[o1 - 64]);
#pragma unroll
        for (int nt = 0; nt < 16; ++nt) {
            acc[nt][0] += bias0; acc[nt][1] += bias0;
            acc[nt][2] += bias1; acc[nt][3] += bias1;
        }
    }

    float* stage = (float*)qsm;
    __syncthreads();
#pragma unroll
    for (int nt = 0; nt < 16; ++nt) {
        const int n = wn * 128 + nt * 8 + 2 * tig;
        const int o0 = wo * 16 + grp;
        stage[n * 68 + o0]           = acc[nt][0];
        stage[(n + 1) * 68 + o0]     = acc[nt][1];
        stage[n * 68 + o0 + 8]       = acc[nt][2];
        stage[(n + 1) * 68 + o0 + 8] = acc[nt][3];
    }
    __syncthreads();

    {
        const int n = tid;
        const float* sr = stage + n * 68;
        if (o_base == 0) {
            float* dq = g_q + ((size_t)b * NTOK + n_base + n) * 32;
            float* dk = g_k + ((size_t)b * NTOK + n_base + n) * 32;
#pragma unroll
            for (int c4 = 0; c4 < 8; ++c4) {
                float4 v = *(const float4*)(sr + c4 * 4);
                *(float4*)(dq + c4 * 4) = make_float4(f2tf32f(v.x), f2tf32f(v.y),
                                                      f2tf32f(v.z), f2tf32f(v.w));
                float4 u = *(const float4*)(sr + 32 + c4 * 4);
                *(float4*)(dk + c4 * 4) = make_float4(f2tf32f(u.x), f2tf32f(u.y),
                                                      f2tf32f(u.z), f2tf32f(u.w));
            }
        } else {
            __nv_bfloat16* dv = g_v + ((size_t)b * NTOK + n_base + n) * CDIM + (o_base - 64);
#pragma unroll
            for (int c4 = 0; c4 < 16; ++c4) {
                float4 v = *(const float4*)(sr + c4 * 4);
                u32 p01, p23;
                asm("cvt.rn.bf16x2.f32 %0, %1, %2;" : "=r"(p01) : "f"(v.y), "f"(v.x));
                asm("cvt.rn.bf16x2.f32 %0, %1, %2;" : "=r"(p23) : "f"(v.w), "f"(v.z));
                *(uint2*)(dv + c4 * 4) = make_uint2(p01, p23);
            }
        }
    }
}

// ---------------------------------------------------------------------------
// Kernel 2: warp-MMA flash attention, r4 shell, TJ=128 (32 iterations).
// 256 threads / 8 warps; warp w = rows w*16..+15, all 256 O cols.
// Per iter: S = Q K^T over 128 keys (two register-bounded halves of 8
// n8-tiles, exp+pack each half into pk[8]); O += P V (cb 0..15, kj 0..7).
// Race-free prefetch-1 cp.async double buffer (sync precedes issue).
// ---------------------------------------------------------------------------
#define KSTR 36        // K smem row stride (floats)
#define VSTR 264       // V smem row stride (bf16)
#define A_BUF (128 * KSTR * 4 + 128 * VSTR * 2)   // 18432 + 67584 = 86016
#define A_SMEM (2 * A_BUF)                         // 172032

__global__ __launch_bounds__(256, 1) void attn_kernel(
    const float* __restrict__ x,
    const float* __restrict__ gamma,
    float* __restrict__ out)
{
    extern __shared__ __align__(16) char smem[];
    const int tid  = threadIdx.x;
    const int w    = tid >> 5;
    const int lane = tid & 31;
    const int grp  = lane >> 2;
    const int tig  = lane & 3;
    const int b    = blockIdx.y;
    const int ibase = blockIdx.x * 128;
    const u32 sbase = smem_u32(smem);

#define ATTN_ISSUE(t, sel) do {                                                  \
        const u32 kb_ = sbase + (u32)(sel) * A_BUF;                              \
        const float4* gk = (const float4*)(g_k + ((size_t)b * NTOK + (t) * 128) * 32); \
        _Pragma("unroll")                                                        \
        for (int u = 0; u < 4; ++u) {                                            \
            const int idx = tid + u * 256;                                       \
            CP16(kb_ + (idx >> 3) * (KSTR * 4) + (idx & 7) * 16, gk + idx);      \
        }                                                                        \
        const u32 vb_ = kb_ + 128 * KSTR * 4;                                    \
        const uint4* gv = (const uint4*)(g_v + ((size_t)b * NTOK + (t) * 128) * CDIM); \
        _Pragma("unroll")                                                        \
        for (int u = 0; u < 16; ++u) {                                           \
            const int idx = tid + u * 256;                                       \
            CP16(vb_ + (idx >> 5) * (VSTR * 2) + (idx & 31) * 16, gv + idx);     \
        }                                                                        \
    } while (0)

    ATTN_ISSUE(0, 0); CP_COMMIT();

    // ---- Q A-fragments (tf32 m16n8k8): rows ibase + w*16 + {grp, grp+8}
    u32 qa[4][4];
    {
        const float* Qb = g_q + ((size_t)b * NTOK + ibase + w * 16) * 32;
#pragma unroll
        for (int ks = 0; ks < 4; ++ks) {
            const int c = ks * 8 + tig;
            qa[ks][0] = __float_as_uint(Qb[grp * 32 + c]);
            qa[ks][1] = __float_as_uint(Qb[(grp + 8) * 32 + c]);
            qa[ks][2] = __float_as_uint(Qb[grp * 32 + c + 4]);
            qa[ks][3] = __float_as_uint(Qb[(grp + 8) * 32 + c + 4]);
        }
    }

    float acc[32][4];
#pragma unroll
    for (int i = 0; i < 32; ++i)
#pragma unroll
        for (int q = 0; q < 4; ++q) acc[i][q] = 0.0f;
    float l0 = 0.0f, l1 = 0.0f;

    const u32 lmoff = (u32)(((lane & 15) * VSTR + ((lane >> 4) * 8)) * 2);

#pragma unroll 1
    for (int t = 0; t < 32; ++t) {
        CP_WAIT(0);
        __syncthreads();
        if (t + 1 < 32) { ATTN_ISSUE(t + 1, (t + 1) & 1); CP_COMMIT(); }

        const int sel = t & 1;
        const float* Ks = (const float*)(smem + sel * A_BUF);
        const u32 lmbase = sbase + (u32)sel * A_BUF + 128 * KSTR * 4 + lmoff;

        // ---- S = Q K^T over 128 keys: two halves of 8 n8-tiles each
        u32 pk[8][4];
#pragma unroll
        for (int h = 0; h < 2; ++h) {
            float p[8][4];
#pragma unroll
            for (int ntl = 0; ntl < 8; ++ntl) {
                const int nt = h * 8 + ntl;
                float s0 = 0.f, s1 = 0.f, s2 = 0.f, s3 = 0.f;
#pragma unroll
                for (int ks = 0; ks < 4; ++ks) {
                    const u32 b0 = __float_as_uint(Ks[(nt * 8 + grp) * KSTR + ks * 8 + tig]);
                    const u32 b1 = __float_as_uint(Ks[(nt * 8 + grp) * KSTR + ks * 8 + 4 + tig]);
                    asm volatile(
                        "mma.sync.aligned.m16n8k8.row.col.f32.tf32.tf32.f32 "
                        "{%0,%1,%2,%3}, {%4,%5,%6,%7}, {%8,%9}, {%0,%1,%2,%3};"
                        : "+f"(s0), "+f"(s1), "+f"(s2), "+f"(s3)
                        : "r"(qa[ks][0]), "r"(qa[ks][1]), "r"(qa[ks][2]), "r"(qa[ks][3]),
                          "r"(b0), "r"(b1));
                }
                p[ntl][0] = __expf(s0);
                p[ntl][1] = __expf(s1);
                p[ntl][2] = __expf(s2);
                p[ntl][3] = __expf(s3);
                l0 += p[ntl][0] + p[ntl][1];
                l1 += p[ntl][2] + p[ntl][3];
            }
#pragma unroll
            for (int kj2 = 0; kj2 < 4; ++kj2) {
                const int kj = h * 4 + kj2;
                asm("cvt.rn.bf16x2.f32 %0, %1, %2;" : "=r"(pk[kj][0]) : "f"(p[2*kj2][1]),   "f"(p[2*kj2][0]));
                asm("cvt.rn.bf16x2.f32 %0, %1, %2;" : "=r"(pk[kj][1]) : "f"(p[2*kj2][3]),   "f"(p[2*kj2][2]));
                asm("cvt.rn.bf16x2.f32 %0, %1, %2;" : "=r"(pk[kj][2]) : "f"(p[2*kj2+1][1]), "f"(p[2*kj2+1][0]));
                asm("cvt.rn.bf16x2.f32 %0, %1, %2;" : "=r"(pk[kj][3]) : "f"(p[2*kj2+1][3]), "f"(p[2*kj2+1][2]));
            }
        }

        // ---- O += P * V   (bf16 m16n8k16): cb 0..15, kj 0..7
#pragma unroll
        for (int cb = 0; cb < 16; ++cb) {
#pragma unroll
            for (int kj = 0; kj < 8; ++kj) {
                u32 r0, r1, r2, r3;
                const u32 addr = lmbase + (u32)(kj * 16 * (VSTR * 2) + cb * 32);
                asm volatile(
                    "ldmatrix.sync.aligned.m8n8.x4.trans.shared.b16 {%0,%1,%2,%3}, [%4];"
                    : "=r"(r0), "=r"(r1), "=r"(r2), "=r"(r3) : "r"(addr));
                asm volatile(
                    "mma.sync.aligned.m16n8k16.row.col.f32.bf16.bf16.f32 "
                    "{%0,%1,%2,%3}, {%4,%5,%6,%7}, {%8,%9}, {%0,%1,%2,%3};"
                    : "+f"(acc[cb*2][0]), "+f"(acc[cb*2][1]), "+f"(acc[cb*2][2]), "+f"(acc[cb*2][3])
                    : "r"(pk[kj][0]), "r"(pk[kj][1]), "r"(pk[kj][2]), "r"(pk[kj][3]),
                      "r"(r0), "r"(r1));
                asm volatile(
                    "mma.sync.aligned.m16n8k16.row.col.f32.bf16.bf16.f32 "
                    "{%0,%1,%2,%3}, {%4,%5,%6,%7}, {%8,%9}, {%0,%1,%2,%3};"
                    : "+f"(acc[cb*2+1][0]), "+f"(acc[cb*2+1][1]), "+f"(acc[cb*2+1][2]), "+f"(acc[cb*2+1][3])
                    : "r"(pk[kj][0]), "r"(pk[kj][1]), "r"(pk[kj][2]), "r"(pk[kj][3]),
                      "r"(r2), "r"(r3));
            }
        }
    }
    __syncthreads();

    // ---- finalize l
    l0 += __shfl_xor_sync(0xFFFFFFFFu, l0, 1);
    l0 += __shfl_xor_sync(0xFFFFFFFFu, l0, 2);
    l1 += __shfl_xor_sync(0xFFFFFFFFu, l1, 1);
    l1 += __shfl_xor_sync(0xFFFFFFFFu, l1, 2);
    const float gval = gamma[0];
    const float invl0 = gval / l0;
    const float invl1 = gval / l1;

    // ---- epilogue (r4): 4 chunks of 64 cols x 128 i, staged via smem
    float* stage = (float*)smem;
#pragma unroll 1
    for (int cc = 0; cc < 4; ++cc) {
#pragma unroll
        for (int nt2 = 0; nt2 < 8; ++nt2) {
            const int nt8 = cc * 8 + nt2;
            const int c0 = nt2 * 8 + 2 * tig;
            const int i0 = w * 16 + grp;
            stage[c0 * 132 + i0]           = acc[nt8][0] * invl0;
            stage[(c0 + 1) * 132 + i0]     = acc[nt8][1] * invl0;
            stage[c0 * 132 + i0 + 8]       = acc[nt8][2] * invl1;
            stage[(c0 + 1) * 132 + i0 + 8] = acc[nt8][3] * invl1;
        }
        __syncthreads();
        {
            const int cl = tid >> 2;
            const int cg = cc * 64 + cl;
            const int ii0 = (tid & 3) * 32;
            const size_t row = ((size_t)b * CDIM + cg) * NTOK + ibase;
#pragma unroll
            for (int u = 0; u < 8; ++u) {
                const int i = ii0 + u * 4;
                const float4 sv = *(const float4*)&stage[cl * 132 + i];
                const float4 xv = *(const float4*)(x + row + i);
                *(float4*)(out + row + i) =
                    make_float4(sv.x + xv.x, sv.y + xv.y, sv.z + xv.z, sv.w + xv.w);
            }
        }
        __syncthreads();
    }
}

// ---------------------------------------------------------------------------
extern "C" void kernel_launch(void* const* d_in, const int* in_sizes, int n_in,
                              void* d_out, int out_size)
{
    const float* x     = (const float*)d_in[0];
    const float* Wq    = (const float*)d_in[1];
    const float* bq    = (const float*)d_in[2];
    const float* Wk    = (const float*)d_in[3];
    const float* bk    = (const float*)d_in[4];
    const float* Wv    = (const float*)d_in[5];
    const float* bv    = (const float*)d_in[6];
    const float* gamma = (const float*)d_in[7];
    float* out = (float*)d_out;

    cudaFuncSetAttribute(qkv_kernel, cudaFuncAttributeMaxDynamicSharedMemorySize, Q_SMEM);
    cudaFuncSetAttribute(attn_kernel, cudaFuncAttributeMaxDynamicSharedMemorySize, A_SMEM);

    qkv_kernel<<<dim3(NTOK / 256, 5, BATCH), 256, Q_SMEM>>>(x, Wq, bq, Wk, bk, Wv, bv);
    attn_kernel<<<dim3(NTOK / 128, BATCH), 256, A_SMEM>>>(x, gamma, out);
}

// round 14
// speedup vs baseline: 1.4013x; 1.0565x over previous
#include <cuda_runtime.h>
#include <cuda_bf16.h>
#include <cstdint>

#define BATCH 8
#define CDIM  256
#define NTOK  4096

typedef unsigned int u32;

// Scratch (allocation-free rule)
__device__ __nv_bfloat16  g_q[BATCH * NTOK * 32];    // [b][n][32] bf16
__device__ __nv_bfloat16  g_k[BATCH * NTOK * 32];    // [b][n][32] bf16
__device__ __nv_bfloat16  g_v[(size_t)BATCH * NTOK * CDIM];  // [b][n][256] bf16

__device__ __forceinline__ u32 smem_u32(const void* p) {
    u32 a;
    asm("{ .reg .u64 t; cvta.to.shared.u64 t, %1; cvt.u32.u64 %0, t; }" : "=r"(a) : "l"(p));
    return a;
}
__device__ __forceinline__ u32 f2tf32u(float x) {
    u32 u; asm("cvt.rna.tf32.f32 %0, %1;" : "=r"(u) : "f"(x));
    return u;
}

#define CP16(dst, src) \
    asm volatile("cp.async.cg.shared.global [%0], [%1], 16;" :: "r"(dst), "l"(src))
#define CP_COMMIT() asm volatile("cp.async.commit_group;" ::: "memory")
#define CP_WAIT(n)  asm volatile("cp.async.wait_group %0;" :: "n"(n) : "memory")

#define LDSM_N(r, addr) \
    asm volatile("ldmatrix.sync.aligned.m8n8.x4.shared.b16 {%0,%1,%2,%3}, [%4];" \
        : "=r"((r)[0]), "=r"((r)[1]), "=r"((r)[2]), "=r"((r)[3]) : "r"(addr))

#define HMMA_BF16(d, a, b0_, b1_) \
    asm volatile("mma.sync.aligned.m16n8k16.row.col.f32.bf16.bf16.f32 " \
        "{%0,%1,%2,%3}, {%4,%5,%6,%7}, {%8,%9}, {%0,%1,%2,%3};" \
        : "+f"((d)[0]), "+f"((d)[1]), "+f"((d)[2]), "+f"((d)[3]) \
        : "r"((a)[0]), "r"((a)[1]), "r"((a)[2]), "r"((a)[3]), "r"(b0_), "r"(b1_))

// ---------------------------------------------------------------------------
// Kernel 1: tensor-core QKV projection (tf32 m16n8k8). Math unchanged from
// r4; q,k now stored bf16 token-major [n][32].
// ---------------------------------------------------------------------------
#define QW_STR 36
#define QX_STR 260
#define Q_BUF  (64 * QW_STR * 4 + 32 * QX_STR * 4)   // 42496
#define Q_SMEM (2 * Q_BUF)                            // 84992

__global__ __launch_bounds__(256, 2) void qkv_kernel(
    const float* __restrict__ x,
    const float* __restrict__ Wq, const float* __restrict__ bq,
    const float* __restrict__ Wk, const float* __restrict__ bk,
    const float* __restrict__ Wv, const float* __restrict__ bv)
{
    extern __shared__ __align__(16) char qsm[];
    const int b      = blockIdx.z;
    const int o_base = blockIdx.y * 64;
    const int n_base = blockIdx.x * 256;
    const int tid    = threadIdx.x;
    const int w      = tid >> 5, lane = tid & 31;
    const int grp    = lane >> 2, tig = lane & 3;
    const int wo     = w & 3, wn = w >> 2;
    const float* xb  = x + (size_t)b * CDIM * NTOK;
    const u32 sbase  = smem_u32(qsm);

    const float* wrowp[2];
    int wcol[2];
    int wdst[2];
#pragma unroll
    for (int u = 0; u < 2; ++u) {
        const int idx = tid + u * 256;
        const int row = idx >> 3;
        const int og  = o_base + row;
        wrowp[u] = (og < 32) ? (Wq + (size_t)og * CDIM)
                 : ((og < 64) ? (Wk + (size_t)(og - 32) * CDIM)
                              : (Wv + (size_t)(og - 64) * CDIM));
        wcol[u]  = (idx & 7) * 4;
        wdst[u]  = row * (QW_STR * 4) + (idx & 7) * 16;
    }

    float acc[16][4];
#pragma unroll
    for (int nt = 0; nt < 16; ++nt)
#pragma unroll
        for (int q = 0; q < 4; ++q) acc[nt][q] = 0.0f;

#define QKV_ISSUE(s, sel) do {                                                   \
        const u32 wb = sbase + (sel) * Q_BUF;                                    \
        _Pragma("unroll")                                                        \
        for (int u = 0; u < 2; ++u)                                              \
            CP16(wb + wdst[u], wrowp[u] + (s) * 32 + wcol[u]);                   \
        const u32 xs = wb + 64 * QW_STR * 4;                                     \
        _Pragma("unroll")                                                        \
        for (int u = 0; u < 8; ++u) {                                            \
            const int idx = tid + u * 256;                                       \
            const int cr = idx >> 6, nc = (idx & 63) * 4;                        \
            CP16(xs + cr * (QX_STR * 4) + nc * 4,                                \
                 xb + (size_t)((s) * 32 + cr) * NTOK + n_base + nc);             \
        }                                                                        \
    } while (0)

    QKV_ISSUE(0, 0); CP_COMMIT();

#pragma unroll 1
    for (int s = 0; s < 8; ++s) {
        if (s < 7) { QKV_ISSUE(s + 1, (s + 1) & 1); CP_COMMIT(); CP_WAIT(1); }
        else       { CP_WAIT(0); }
        __syncthreads();
        const float* sW = (const float*)(qsm + (s & 1) * Q_BUF);
        const float* sX = sW + 64 * QW_STR;
#pragma unroll
        for (int ks = 0; ks < 4; ++ks) {
            const int c = ks * 8 + tig;
            u32 a0 = f2tf32u(sW[(wo * 16 + grp) * QW_STR + c]);
            u32 a1 = f2tf32u(sW[(wo * 16 + grp + 8) * QW_STR + c]);
            u32 a2 = f2tf32u(sW[(wo * 16 + grp) * QW_STR + c + 4]);
            u32 a3 = f2tf32u(sW[(wo * 16 + grp + 8) * QW_STR + c + 4]);
#pragma unroll
            for (int nt = 0; nt < 16; ++nt) {
                const int n = wn * 128 + nt * 8 + grp;
                const u32 b0 = __float_as_uint(sX[(ks * 8 + tig) * QX_STR + n]);
                const u32 b1 = __float_as_uint(sX[(ks * 8 + tig + 4) * QX_STR + n]);
                asm volatile(
                    "mma.sync.aligned.m16n8k8.row.col.f32.tf32.tf32.f32 "
                    "{%0,%1,%2,%3}, {%4,%5,%6,%7}, {%8,%9}, {%0,%1,%2,%3};"
                    : "+f"(acc[nt][0]), "+f"(acc[nt][1]), "+f"(acc[nt][2]), "+f"(acc[nt][3])
                    : "r"(a0), "r"(a1), "r"(a2), "r"(a3), "r"(b0), "r"(b1));
            }
        }
        __syncthreads();
    }

    {
        const int o0 = o_base + wo * 16 + grp;
        const int o1 = o0 + 8;
        const float bias0 = (o0 < 32) ? bq[o0] : ((o0 < 64) ? bk[o0 - 32] : bv[o0 - 64]);
        const float bias1 = (o1 < 32) ? bq[o1] : ((o1 < 64) ? bk[o1 - 32] : bv[o1 - 64]);
#pragma unroll
        for (int nt = 0; nt < 16; ++nt) {
            acc[nt][0] += bias0; acc[nt][1] += bias0;
            acc[nt][2] += bias1; acc[nt][3] += bias1;
        }
    }

    float* stage = (float*)qsm;
    __syncthreads();
#pragma unroll
    for (int nt = 0; nt < 16; ++nt) {
        const int n = wn * 128 + nt * 8 + 2 * tig;
        const int o0 = wo * 16 + grp;
        stage[n * 68 + o0]           = acc[nt][0];
        stage[(n + 1) * 68 + o0]     = acc[nt][1];
        stage[n * 68 + o0 + 8]       = acc[nt][2];
        stage[(n + 1) * 68 + o0 + 8] = acc[nt][3];
    }
    __syncthreads();

    {
        const int n = tid;
        const float* sr = stage + n * 68;
        if (o_base == 0) {
            __nv_bfloat16* dq = g_q + ((size_t)b * NTOK + n_base + n) * 32;
            __nv_bfloat16* dk = g_k + ((size_t)b * NTOK + n_base + n) * 32;
#pragma unroll
            for (int c4 = 0; c4 < 8; ++c4) {
                float4 v = *(const float4*)(sr + c4 * 4);
                u32 p01, p23;
                asm("cvt.rn.bf16x2.f32 %0, %1, %2;" : "=r"(p01) : "f"(v.y), "f"(v.x));
                asm("cvt.rn.bf16x2.f32 %0, %1, %2;" : "=r"(p23) : "f"(v.w), "f"(v.z));
                *(uint2*)(dq + c4 * 4) = make_uint2(p01, p23);
                float4 u = *(const float4*)(sr + 32 + c4 * 4);
                asm("cvt.rn.bf16x2.f32 %0, %1, %2;" : "=r"(p01) : "f"(u.y), "f"(u.x));
                asm("cvt.rn.bf16x2.f32 %0, %1, %2;" : "=r"(p23) : "f"(u.w), "f"(u.z));
                *(uint2*)(dk + c4 * 4) = make_uint2(p01, p23);
            }
        } else {
            __nv_bfloat16* dv = g_v + ((size_t)b * NTOK + n_base + n) * CDIM + (o_base - 64);
#pragma unroll
            for (int c4 = 0; c4 < 16; ++c4) {
                float4 v = *(const float4*)(sr + c4 * 4);
                u32 p01, p23;
                asm("cvt.rn.bf16x2.f32 %0, %1, %2;" : "=r"(p01) : "f"(v.y), "f"(v.x));
                asm("cvt.rn.bf16x2.f32 %0, %1, %2;" : "=r"(p23) : "f"(v.w), "f"(v.z));
                *(uint2*)(dv + c4 * 4) = make_uint2(p01, p23);
            }
        }
    }
}

// ---------------------------------------------------------------------------
// Kernel 2: warp-MMA flash attention, TJ=128, bf16 S via ldmatrix K frags.
// 256 threads / 8 warps; warp w = rows w*16..+15, all 256 O cols.
// K smem [128 j][40 bf16] (80B pitch -> conflict-free ldmatrix non-trans).
// Per iter: S over 128 keys (8 tile-pairs, each 2 LDSM.x4 + 4 bf16 HMMA),
// exp+pack -> pk[8]; O += P V (cb 0..15, kj 0..7).
// ---------------------------------------------------------------------------
#define KSTRH 40       // K smem row stride (bf16) = 80 B
#define VSTR 264       // V smem row stride (bf16)
#define K_BYTES (128 * KSTRH * 2)                 // 10240
#define A_BUF (K_BYTES + 128 * VSTR * 2)          // 10240 + 67584 = 77824
#define A_SMEM (2 * A_BUF)                        // 155648

__global__ __launch_bounds__(256, 1) void attn_kernel(
    const float* __restrict__ x,
    const float* __restrict__ gamma,
    float* __restrict__ out)
{
    extern __shared__ __align__(16) char smem[];
    const int tid  = threadIdx.x;
    const int w    = tid >> 5;
    const int lane = tid & 31;
    const int grp  = lane >> 2;
    const int tig  = lane & 3;
    const int b    = blockIdx.y;
    const int ibase = blockIdx.x * 128;
    const u32 sbase = smem_u32(smem);

#define ATTN_ISSUE(t, sel) do {                                                  \
        const u32 kb_ = sbase + (u32)(sel) * A_BUF;                              \
        _Pragma("unroll")                                                        \
        for (int u = 0; u < 2; ++u) {                                            \
            const int idx = tid + u * 256;                                       \
            const int row = idx >> 2, c16 = idx & 3;                             \
            CP16(kb_ + row * (KSTRH * 2) + c16 * 16,                             \
                 g_k + ((size_t)b * NTOK + (t) * 128 + row) * 32 + c16 * 8);     \
        }                                                                        \
        const u32 vb_ = kb_ + K_BYTES;                                           \
        const uint4* gv = (const uint4*)(g_v + ((size_t)b * NTOK + (t) * 128) * CDIM); \
        _Pragma("unroll")                                                        \
        for (int u = 0; u < 16; ++u) {                                           \
            const int idx = tid + u * 256;                                       \
            CP16(vb_ + (idx >> 5) * (VSTR * 2) + (idx & 31) * 16, gv + idx);     \
        }                                                                        \
    } while (0)

    ATTN_ISSUE(0, 0); CP_COMMIT();

    // ---- Q A-fragments (bf16 m16n8k16): rows ibase + w*16 + {grp, grp+8},
    // two k16 chunks over the 32 channels
    u32 qa[2][4];
    {
        const __nv_bfloat16* Qb = g_q + ((size_t)b * NTOK + ibase + w * 16) * 32;
#pragma unroll
        for (int kc = 0; kc < 2; ++kc) {
            const int c = kc * 16 + 2 * tig;
            qa[kc][0] = *(const u32*)(Qb + grp * 32 + c);
            qa[kc][1] = *(const u32*)(Qb + (grp + 8) * 32 + c);
            qa[kc][2] = *(const u32*)(Qb + grp * 32 + c + 8);
            qa[kc][3] = *(const u32*)(Qb + (grp + 8) * 32 + c + 8);
        }
    }

    float acc[32][4];
#pragma unroll
    for (int i = 0; i < 32; ++i)
#pragma unroll
        for (int q = 0; q < 4; ++q) acc[i][q] = 0.0f;
    float l0 = 0.0f, l1 = 0.0f;

    const u32 lmoff = (u32)(((lane & 15) * VSTR + ((lane >> 4) * 8)) * 2);
    // K ldmatrix per-lane address offset: matrix m = lane>>3,
    //   j-within-pair = (m>>1)*8 + (lane&7), col16B = (m&1)
    const u32 kfoff = (u32)((((lane >> 4) * 8 + (lane & 7)) * KSTRH * 2) + ((lane >> 3) & 1) * 16);

#pragma unroll 1
    for (int t = 0; t < 32; ++t) {
        CP_WAIT(0);
        __syncthreads();
        if (t + 1 < 32) { ATTN_ISSUE(t + 1, (t + 1) & 1); CP_COMMIT(); }

        const int sel = t & 1;
        const u32 kfb = sbase + (u32)sel * A_BUF + kfoff;
        const u32 lmbase = sbase + (u32)sel * A_BUF + K_BYTES + lmoff;

        // ---- S = Q K^T over 128 keys (bf16): 8 tile-pairs
        u32 pk[8][4];
#pragma unroll
        for (int h = 0; h < 2; ++h) {
#pragma unroll
            for (int ntp = 0; ntp < 4; ++ntp) {
                const int j0 = (h * 8 + ntp * 2) * 8;   // 16 j rows per pair
                u32 kb0[4], kb1[4];
                const u32 ab = kfb + (u32)(j0 * (KSTRH * 2));
                LDSM_N(kb0, ab);        // chunk0: c 0..15
                LDSM_N(kb1, ab + 32);   // chunk1: c 16..31
                float sacA[4] = {0.f, 0.f, 0.f, 0.f};
                float sacB[4] = {0.f, 0.f, 0.f, 0.f};
                HMMA_BF16(sacA, qa[0], kb0[0], kb0[1]);
                HMMA_BF16(sacB, qa[0], kb0[2], kb0[3]);
                HMMA_BF16(sacA, qa[1], kb1[0], kb1[1]);
                HMMA_BF16(sacB, qa[1], kb1[2], kb1[3]);
                const float pA0 = __expf(sacA[0]);
                const float pA1 = __expf(sacA[1]);
                const float pA2 = __expf(sacA[2]);
                const float pA3 = __expf(sacA[3]);
                const float pB0 = __expf(sacB[0]);
                const float pB1 = __expf(sacB[1]);
                const float pB2 = __expf(sacB[2]);
                const float pB3 = __expf(sacB[3]);
                l0 += pA0 + pA1 + pB0 + pB1;
                l1 += pA2 + pA3 + pB2 + pB3;
                const int kj = h * 4 + ntp;
                asm("cvt.rn.bf16x2.f32 %0, %1, %2;" : "=r"(pk[kj][0]) : "f"(pA1), "f"(pA0));
                asm("cvt.rn.bf16x2.f32 %0, %1, %2;" : "=r"(pk[kj][1]) : "f"(pA3), "f"(pA2));
                asm("cvt.rn.bf16x2.f32 %0, %1, %2;" : "=r"(pk[kj][2]) : "f"(pB1), "f"(pB0));
                asm("cvt.rn.bf16x2.f32 %0, %1, %2;" : "=r"(pk[kj][3]) : "f"(pB3), "f"(pB2));
            }
        }

        // ---- O += P * V   (bf16 m16n8k16): cb 0..15, kj 0..7
#pragma unroll
        for (int cb = 0; cb < 16; ++cb) {
#pragma unroll
            for (int kj = 0; kj < 8; ++kj) {
                u32 r[4];
                const u32 addr = lmbase + (u32)(kj * 16 * (VSTR * 2) + cb * 32);
                asm volatile(
                    "ldmatrix.sync.aligned.m8n8.x4.trans.shared.b16 {%0,%1,%2,%3}, [%4];"
                    : "=r"(r[0]), "=r"(r[1]), "=r"(r[2]), "=r"(r[3]) : "r"(addr));
                HMMA_BF16(acc[cb * 2],     pk[kj], r[0], r[1]);
                HMMA_BF16(acc[cb * 2 + 1], pk[kj], r[2], r[3]);
            }
        }
    }
    __syncthreads();

    // ---- finalize l
    l0 += __shfl_xor_sync(0xFFFFFFFFu, l0, 1);
    l0 += __shfl_xor_sync(0xFFFFFFFFu, l0, 2);
    l1 += __shfl_xor_sync(0xFFFFFFFFu, l1, 1);
    l1 += __shfl_xor_sync(0xFFFFFFFFu, l1, 2);
    const float gval = gamma[0];
    const float invl0 = gval / l0;
    const float invl1 = gval / l1;

    // ---- epilogue: 4 chunks of 64 cols x 128 i, staged via smem
    float* stage = (float*)smem;
#pragma unroll 1
    for (int cc = 0; cc < 4; ++cc) {
#pragma unroll
        for (int nt2 = 0; nt2 < 8; ++nt2) {
            const int nt8 = cc * 8 + nt2;
            const int c0 = nt2 * 8 + 2 * tig;
            const int i0 = w * 16 + grp;
            stage[c0 * 132 + i0]           = acc[nt8][0] * invl0;
            stage[(c0 + 1) * 132 + i0]     = acc[nt8][1] * invl0;
            stage[c0 * 132 + i0 + 8]       = acc[nt8][2] * invl1;
            stage[(c0 + 1) * 132 + i0 + 8] = acc[nt8][3] * invl1;
        }
        __syncthreads();
        {
            const int cl = tid >> 2;
            const int cg = cc * 64 + cl;
            const int ii0 = (tid & 3) * 32;
            const size_t row = ((size_t)b * CDIM + cg) * NTOK + ibase;
#pragma unroll
            for (int u = 0; u < 8; ++u) {
                const int i = ii0 + u * 4;
                const float4 sv = *(const float4*)&stage[cl * 132 + i];
                const float4 xv = *(const float4*)(x + row + i);
                *(float4*)(out + row + i) =
                    make_float4(sv.x + xv.x, sv.y + xv.y, sv.z + xv.z, sv.w + xv.w);
            }
        }
        __syncthreads();
    }
}

// ---------------------------------------------------------------------------
extern "C" void kernel_launch(void* const* d_in, const int* in_sizes, int n_in,
                              void* d_out, int out_size)
{
    const float* x     = (const float*)d_in[0];
    const float* Wq    = (const float*)d_in[1];
    const float* bq    = (const float*)d_in[2];
    const float* Wk    = (const float*)d_in[3];
    const float* bk    = (const float*)d_in[4];
    const float* Wv    = (const float*)d_in[5];
    const float* bv    = (const float*)d_in[6];
    const float* gamma = (const float*)d_in[7];
    float* out = (float*)d_out;

    cudaFuncSetAttribute(qkv_kernel, cudaFuncAttributeMaxDynamicSharedMemorySize, Q_SMEM);
    cudaFuncSetAttribute(attn_kernel, cudaFuncAttributeMaxDynamicSharedMemorySize, A_SMEM);

    qkv_kernel<<<dim3(NTOK / 256, 5, BATCH), 256, Q_SMEM>>>(x, Wq, bq, Wk, bk, Wv, bv);
    attn_kernel<<<dim3(NTOK / 128, BATCH), 256, A_SMEM>>>(x, gamma, out);
}